// round 7
// baseline (speedup 1.0000x reference)
#include <cuda_runtime.h>

// CubicShapeFunction: 500K points, 4^3 cubic B-spline stencil.
// Output layout (flat float32):
//   [0, N*64)             shapef [N,64]
//   [N*64, N*64+N*192)    grad   [N,64,3]
//
// R6: persistent single-wave grid (148 SM x 8 blocks) grid-striding over
// 31250 tiles of 16 points. Inner structure identical to R5 (warp-synchronous,
// SMEM-transposed grad drain, all STG.128 coalesced). Removes ~25 wave
// transitions and lets tile i's drain overlap tile i+1's table build.

constexpr int   N_POINTS      = 500000;
constexpr float INV_CELL      = 20.0f;
constexpr int   PTS_PER_BLOCK = 16;     // 8 warps x 2 points; 500000 % 16 == 0
constexpr int   THREADS       = 256;
constexpr int   N_TILES       = N_POINTS / PTS_PER_BLOCK;   // 31250
constexpr int   GRID          = 148 * 8;                    // one full wave

__global__ __launch_bounds__(THREADS, 8)
void cubic_shape_kernel(const float* __restrict__ pos, float* __restrict__ out) {
    __shared__ float  s_b [PTS_PER_BLOCK][3][4];   // basis
    __shared__ float  s_db[PTS_PER_BLOCK][3][4];   // d(basis)*INV_CELL
    __shared__ float4 s_gr[PTS_PER_BLOCK * 48];    // 768 float4 = 12 KB grad staging

    const int tid  = threadIdx.x;
    const int wid  = tid >> 5;          // warp id: owns points {2w, 2w+1}
    const int lane = tid & 31;

    // Phase-1 lane decode (loop-invariant)
    const int p1_p    = lane / 12;          // 0 or 1 within warp
    const int p1_r    = lane % 12;
    const int p1_axis = p1_r >> 2;
    const int p1_o    = p1_r & 3;
    const int p1_pl   = wid * 2 + p1_p;
    const bool p1_act = (lane < 24);

    // Phase-2 lane decode (loop-invariant)
    const int p2_pl = wid * 2 + (lane >> 4);
    const int p2_ij = lane & 15;
    const int p2_i  = p2_ij >> 2;
    const int p2_j  = p2_ij & 3;

    float4* const osf_base = (float4*)out;
    float4* const ogr_base = (float4*)(out + (size_t)N_POINTS * 64);

    for (int tile = blockIdx.x; tile < N_TILES; tile += GRID) {
        const int pt0 = tile * PTS_PER_BLOCK;

        // ---- Phase 1 (warp-local): 24 lanes build spline table for 2 points ----
        if (p1_act) {
            const float pp   = pos[(pt0 + p1_pl) * 3 + p1_axis];
            const float rel  = pp * INV_CELL;                 // ORIGIN = 0
            const float base = floorf(rel) - 1.0f;
            const float x    = rel - (base + (float)p1_o);    // matches reference expr

            float bb, dd;
            if (p1_o == 0) {         // x in [1,2): c4 branch
                bb = (((-1.0f/6.0f) * x + 1.0f) * x - 2.0f) * x + 4.0f/3.0f;
                dd = (-0.5f * x + 2.0f) * x - 2.0f;
            } else if (p1_o == 1) {  // x in [0,1): c3 branch
                bb = (0.5f * x - 1.0f) * x * x + 2.0f/3.0f;
                dd = (1.5f * x - 2.0f) * x;
            } else if (p1_o == 2) {  // x in [-1,0): c2 branch
                bb = (-0.5f * x - 1.0f) * x * x + 2.0f/3.0f;
                dd = (-1.5f * x - 2.0f) * x;
            } else {                 // x in [-2,-1): c1 branch
                bb = (((1.0f/6.0f) * x + 1.0f) * x + 2.0f) * x + 4.0f/3.0f;
                dd = (0.5f * x + 2.0f) * x + 2.0f;
            }
            s_b [p1_pl][p1_axis][p1_o] = bb;
            s_db[p1_pl][p1_axis][p1_o] = INV_CELL * dd;
        }
        __syncwarp();

        // ---- Phase 2 (warp-local): lane = (point, i, j); k vectorized ----
        {
            const float bx  = s_b [p2_pl][0][p2_i];
            const float by  = s_b [p2_pl][1][p2_j];
            const float dbx = s_db[p2_pl][0][p2_i];
            const float dby = s_db[p2_pl][1][p2_j];
            const float4 bz  = *(const float4*)s_b [p2_pl][2];
            const float4 dbz = *(const float4*)s_db[p2_pl][2];

            const float bxy   = bx * by;
            const float dbx_y = dbx * by;
            const float dby_x = dby * bx;

            // shapef: consecutive tid -> consecutive float4, fully coalesced
            const float4 sf = make_float4(bxy * bz.x, bxy * bz.y, bxy * bz.z, bxy * bz.w);
            __stcs(&osf_base[(size_t)pt0 * 16 + tid], sf);

            // grad entry k: ( dbx*by*bz[k], dby*bx*bz[k], dbz[k]*bx*by )
            float4 g0 = make_float4(dbx_y * bz.x, dby_x * bz.x, dbz.x * bxy,
                                    dbx_y * bz.y);
            float4 g1 = make_float4(dby_x * bz.y, dbz.y * bxy,
                                    dbx_y * bz.z, dby_x * bz.z);
            float4 g2 = make_float4(dbz.z * bxy,
                                    dbx_y * bz.w, dby_x * bz.w, dbz.w * bxy);

            float4* g = &s_gr[(p2_pl * 16 + p2_ij) * 3];
            g[0] = g0;
            g[1] = g1;
            g[2] = g2;
        }
        __syncwarp();

        // ---- Phase 3 (warp-local): drain this warp's 96 float4, coalesced ----
        {
            float4* ogr = ogr_base + (size_t)tile * (PTS_PER_BLOCK * 48);
            const int base = wid * 96;
            #pragma unroll
            for (int r = 0; r < 3; r++) {
                const int idx = base + r * 32 + lane;
                __stcs(&ogr[idx], s_gr[idx]);
            }
        }
        __syncwarp();   // staging reuse guard for next tile (warp-private deps)
    }
}

extern "C" void kernel_launch(void* const* d_in, const int* in_sizes, int n_in,
                              void* d_out, int out_size) {
    const float* pos = (const float*)d_in[0];
    float* out = (float*)d_out;
    cubic_shape_kernel<<<GRID, THREADS>>>(pos, out);
}